// round 12
// baseline (speedup 1.0000x reference)
#include <cuda_runtime.h>
#include <math_constants.h>

// Problem constants (fixed by the bench)
#define TRAJ  8
#define EVAL  30
#define NB    2048          // trajectories
#define NG    256           // groups = NB/TRAJ
#define HALF  15            // evals per half-block
#define WM    400           // nx
#define HM    400           // ny
#define DM    64            // nz
#define VOXF  0.2f
#define INV_VOX 5.0f        // 1/0.2 exactly representable
#define NPTS  (TRAJ * EVAL) // 240 points per group
#define NBLK  (NG * 2)      // 512 blocks, 2 per group

// -------- persistent device scratch (no allocations allowed) --------
__device__ int4 g_bmin[NG];      // trunc'd voxel min per group (x,y,z,_)
__device__ int4 g_bmax[NG];      // trunc'd voxel max per group

// ticket barrier: monotonically increasing across replays -> replay-safe,
// no reset store needed. target = (my_ticket/NBLK + 1) * NBLK.
__device__ unsigned g_count = 0;

__global__ void __launch_bounds__(256, 4)
kFused(const float* __restrict__ Df,
       const float* __restrict__ Dp,
       const float* __restrict__ L,
       const float* __restrict__ sdf,
       const float* __restrict__ minb,
       const float* __restrict__ shapes,
       const int*   __restrict__ map_id,
       float*       __restrict__ out)
{
    const int g    = blockIdx.x >> 1;     // group
    const int half = blockIdx.x & 1;      // eval-half handled by this block
    const int tid  = threadIdx.x;
    const int lane = tid & 31;
    const int wrp  = tid >> 5;

    __shared__ float scoe[TRAJ][3][6];
    __shared__ float rmn[8][3], rmx[8][3];
    __shared__ int   s_red[8][3];         // cross-warp int max scratch
    __shared__ int   s_wmn[3], s_wls[3];
    __shared__ float s_org[3], s_ginv[3];
    __shared__ float s_mb[3];
    __shared__ int   s_m;
    __shared__ float s_cost[NPTS];

    if (tid == 0) s_m = __ldg(&map_id[g]);

    // hoist phase-2 inputs (pure function of inputs -> legal pre-barrier):
    // thread tid handles group tid in phase 2.
    const int m2 = __ldg(&map_id[tid]);

    __syncthreads();
    const int m = s_m;
    if (tid < 3) s_mb[tid] = __ldg(&minb[m * 3 + tid]);

    int shp2[3];
    #pragma unroll
    for (int c = 0; c < 3; c++) shp2[c] = (int)__ldg(&shapes[m2 * 3 + c]);

    // ---------------- Phase 1: coefficients ------------------------------
    if (tid < TRAJ * 3) {
        const int traj = tid / 3;
        const int c    = tid % 3;
        const int b    = g * TRAJ + traj;
        float d[6];
        #pragma unroll
        for (int s = 0; s < 3; s++) {
            d[s]     = Df[b * 9 + c * 3 + s];
            d[3 + s] = Dp[b * 9 + c * 3 + s];
        }
        #pragma unroll
        for (int j = 0; j < 6; j++) {
            float a = 0.f;
            #pragma unroll
            for (int k = 0; k < 6; k++) a += L[j * 6 + k] * d[k];
            scoe[traj][c][j] = a;
        }
    }
    if (half == 0 && tid < TRAJ) out[g * TRAJ + tid] = 0.f;
    __syncthreads();

    // ---------------- positions (registers) -------------------------------
    float px = 0.f, py = 0.f, pz = 0.f;
    const int  my_ev = tid % EVAL;
    const bool mine  = (tid < NPTS) &&
                       (my_ev >= half * HALF) && (my_ev < half * HALF + HALF);

    float mnx =  CUDART_INF_F, mny =  CUDART_INF_F, mnz =  CUDART_INF_F;
    float mxx = -CUDART_INF_F, mxy = -CUDART_INF_F, mxz = -CUDART_INF_F;

    if (tid < NPTS) {
        const int traj = tid / EVAL;
        const float t = (float)((double)(my_ev + 1) * (2.0 / 30.0));
        float tp[6];
        tp[0] = 1.f;
        #pragma unroll
        for (int k = 1; k < 6; k++) tp[k] = tp[k - 1] * t;

        float p[3];
        #pragma unroll
        for (int c = 0; c < 3; c++) {
            float a = 0.f;
            #pragma unroll
            for (int k = 0; k < 6; k++) a += tp[k] * scoe[traj][c][k];
            p[c] = a;
        }
        px = p[0]; py = p[1]; pz = p[2];
        mnx = mxx = px; mny = mxy = py; mnz = mxz = pz;
    }

    // ---- Speculative corner loads (values -> registers), overlap barrier --
    int l0px = 0, l0py = 0, l0pz = 0;
    float v[8];
    #pragma unroll
    for (int i = 0; i < 8; i++) v[i] = 0.f;
    if (mine) {
        l0px = (int)floorf((px - s_mb[0]) * INV_VOX);
        l0py = (int)floorf((py - s_mb[1]) * INV_VOX);
        l0pz = (int)floorf((pz - s_mb[2]) * INV_VOX);
        const float* base = sdf + (size_t)m * DM * HM * WM;
        #pragma unroll
        for (int dx = 0; dx < 2; dx++) {
            const int igx = min(max(l0px + dx, 0), WM - 1);
            #pragma unroll
            for (int dy = 0; dy < 2; dy++) {
                const int igy = min(max(l0py + dy, 0), HM - 1);
                #pragma unroll
                for (int dz = 0; dz < 2; dz++) {
                    const int igz = min(max(l0pz + dz, 0), DM - 1);
                    v[dx * 4 + dy * 2 + dz] =
                        __ldg(&base[((size_t)igz * HM + igy) * WM + igx]);
                }
            }
        }
    }

    // ---------------- group min/max (butterfly: all lanes hold result) ----
    #pragma unroll
    for (int o = 16; o; o >>= 1) {
        mnx = fminf(mnx, __shfl_xor_sync(0xffffffffu, mnx, o));
        mny = fminf(mny, __shfl_xor_sync(0xffffffffu, mny, o));
        mnz = fminf(mnz, __shfl_xor_sync(0xffffffffu, mnz, o));
        mxx = fmaxf(mxx, __shfl_xor_sync(0xffffffffu, mxx, o));
        mxy = fmaxf(mxy, __shfl_xor_sync(0xffffffffu, mxy, o));
        mxz = fmaxf(mxz, __shfl_xor_sync(0xffffffffu, mxz, o));
    }
    if (lane == 0) {
        rmn[wrp][0] = mnx; rmn[wrp][1] = mny; rmn[wrp][2] = mnz;
        rmx[wrp][0] = mxx; rmx[wrp][1] = mxy; rmx[wrp][2] = mxz;
    }
    __syncthreads();

    // 6 threads publish bounds in parallel (c = tid>>1, max if tid&1)
    if (half == 0 && tid < 6) {
        const int  c     = tid >> 1;
        const bool isMax = tid & 1;
        float r = isMax ? rmx[0][c] : rmn[0][c];
        #pragma unroll
        for (int w = 1; w < 8; w++)
            r = isMax ? fmaxf(r, rmx[w][c]) : fminf(r, rmn[w][c]);
        // trunc toward zero after EXACT division (matches jnp.trunc)
        const int b = (int)__fdiv_rn(r - s_mb[c], VOXF);
        if (isMax) ((int*)&g_bmax[g])[c] = b;
        else       ((int*)&g_bmin[g])[c] = b;
    }

    // ---------------- Global ticket barrier (replay-safe) ------------------
    if (tid == 0) {
        __threadfence();
        const unsigned ticket = atomicAdd(&g_count, 1u);
        const unsigned target = (ticket / NBLK + 1u) * NBLK;
        while (*(volatile unsigned*)&g_count < target) { }
        __threadfence();
    }
    __syncthreads();

    // ---------------- Phase 2: reductions via shuffles ---------------------
    {
        const int4 bmn = g_bmin[tid];     // LDG.128
        const int4 bmx = g_bmax[tid];     // LDG.128
        int mn[3] = { bmn.x, bmn.y, bmn.z };
        int mx[3] = { bmx.x, bmx.y, bmx.z };

        // global max span: warp butterfly + cross-warp smem
        int sp[3];
        #pragma unroll
        for (int c = 0; c < 3; c++) {
            int s = mx[c] - mn[c];
            #pragma unroll
            for (int o = 16; o; o >>= 1)
                s = max(s, __shfl_xor_sync(0xffffffffu, s, o));
            sp[c] = s;
        }
        if (lane == 0) { s_red[wrp][0] = sp[0]; s_red[wrp][1] = sp[1]; s_red[wrp][2] = sp[2]; }
        __syncthreads();
        int span[3];
        #pragma unroll
        for (int c = 0; c < 3; c++) {
            int s = s_red[0][c];
            #pragma unroll
            for (int w = 1; w < 8; w++) s = max(s, s_red[w][c]);
            span[c] = s;
        }
        __syncthreads();   // protect s_red before reuse

        // per-group clip (thread tid = group tid), then global max shift
        int lA[3], lB[3], sh[3];
        #pragma unroll
        for (int c = 0; c < 3; c++) {
            const int cc = (mn[c] + mx[c]) >> 1;      // Python floor-div by 2
            int a  = cc - (span[c] >> 1) - 5;
            int bx = cc + (span[c] >> 1) + 5;
            const int na = max(a, 0);
            bx += na - a; a = na;
            const int nb = min(bx, shp2[c]);
            a -= bx - nb; bx = nb;
            lA[c] = a; lB[c] = bx;
            int s = (a < 0) ? -a : 0;
            #pragma unroll
            for (int o = 16; o; o >>= 1)
                s = max(s, __shfl_xor_sync(0xffffffffu, s, o));
            sh[c] = s;
        }
        if (lane == 0) { s_red[wrp][0] = sh[0]; s_red[wrp][1] = sh[1]; s_red[wrp][2] = sh[2]; }
        __syncthreads();

        // thread g already holds group g's lA/lB in registers -> publish window
        if (tid == g) {
            #pragma unroll
            for (int c = 0; c < 3; c++) {
                int s = s_red[0][c];
                #pragma unroll
                for (int w = 1; w < 8; w++) s = max(s, s_red[w][c]);
                const int a  = lA[c] + s;
                const int ls = lB[c] - a;
                s_wmn[c]  = a;
                s_wls[c]  = ls;
                s_org[c]  = (float)a * VOXF + s_mb[c];
                s_ginv[c] = __fdiv_rn(2.0f, (float)(ls - 1));
            }
        }
        __syncthreads();
    }

    // ---------------- Phase 3: trilinear interp + cost ---------------------
    {
        const int mnX = s_wmn[0], mnY = s_wmn[1], mnZ = s_wmn[2];
        const int lsX = s_wls[0], lsY = s_wls[1], lsZ = s_wls[2];
        const float ogX = s_org[0], ogY = s_org[1], ogZ = s_org[2];
        const float ivX = s_ginv[0], ivY = s_ginv[1], ivZ = s_ginv[2];

        float cost = 0.f;
        if (mine) {
            const float gx = (px - ogX) * INV_VOX;
            const float gy = (py - ogY) * INV_VOX;
            const float gz = (pz - ogZ) * INV_VOX;

            const float gpx = fmaf(gx, ivX, -1.0f);
            const float gpy = fmaf(gy, ivY, -1.0f);
            const float gpz = fmaf(gz, ivZ, -1.0f);
            const bool valid = (gpx < 0.99f) && (gpx > -0.99f) &&
                               (gpy < 0.99f) && (gpy > -0.99f) &&
                               (gpz < 0.99f) && (gpz > -0.99f);

            const float flx = floorf(gx), fly = floorf(gy), flz = floorf(gz);
            const int l0x = (int)flx, l0y = (int)fly, l0z = (int)flz;
            const float fx = gx - flx, fy = gy - fly, fz = gz - flz;

            // verify speculation: predicted global l0 vs exact (l0 + mn)
            const bool match = (l0x + mnX == l0px) &&
                               (l0y + mnY == l0py) &&
                               (l0z + mnZ == l0pz);
            if (!match) {   // rare FP-rounding flip: exact reload
                const float* base = sdf + (size_t)m * DM * HM * WM;
                #pragma unroll
                for (int dx = 0; dx < 2; dx++) {
                    const int igx = min(max(l0x + dx + mnX, 0), WM - 1);
                    #pragma unroll
                    for (int dy = 0; dy < 2; dy++) {
                        const int igy = min(max(l0y + dy + mnY, 0), HM - 1);
                        #pragma unroll
                        for (int dz = 0; dz < 2; dz++) {
                            const int igz = min(max(l0z + dz + mnZ, 0), DM - 1);
                            v[dx * 4 + dy * 2 + dz] =
                                __ldg(&base[((size_t)igz * HM + igy) * WM + igx]);
                        }
                    }
                }
            }

            float acc = 0.f;
            #pragma unroll
            for (int dx = 0; dx < 2; dx++) {
                const float wx = dx ? fx : (1.0f - fx);
                const int  ilx = l0x + dx;
                const bool okx = (ilx >= 0) && (ilx < lsX);
                #pragma unroll
                for (int dy = 0; dy < 2; dy++) {
                    const float wy = dy ? fy : (1.0f - fy);
                    const int  ily = l0y + dy;
                    const bool oky = (ily >= 0) && (ily < lsY);
                    #pragma unroll
                    for (int dz = 0; dz < 2; dz++) {
                        const float wz = dz ? fz : (1.0f - fz);
                        const int  ilz = l0z + dz;
                        const bool okz = (ilz >= 0) && (ilz < lsZ);
                        if (okx && oky && okz)
                            acc += (wx * wy * wz) * v[dx * 4 + dy * 2 + dz];
                    }
                }
            }
            const float e = (acc - 0.5f) * (1.0f / 0.3f);
            cost = valid ? __expf(-e) : 0.f;
        }
        if (mine) s_cost[tid] = cost;
    }
    __syncthreads();

    // per-trajectory sum of this half's 15 evals (fixed order, deterministic)
    if (tid < TRAJ) {
        float s = 0.f;
        const int base = tid * EVAL + half * HALF;
        #pragma unroll
        for (int i = 0; i < HALF; i++) s += s_cost[base + i];
        atomicAdd(&out[g * TRAJ + tid], s * (float)(2.0 / 30.0));
    }
}

// ---------------------------------------------------------------
extern "C" void kernel_launch(void* const* d_in, const int* in_sizes, int n_in,
                              void* d_out, int out_size)
{
    const float* Df   = (const float*)d_in[0];
    const float* Dp   = (const float*)d_in[1];
    const float* L    = (const float*)d_in[2];
    const float* sdf  = (const float*)d_in[3];
    const float* minb = (const float*)d_in[4];
    const float* shp  = (const float*)d_in[5];
    const int*   mid  = (const int*)d_in[6];

    kFused<<<NBLK, 256>>>(Df, Dp, L, sdf, minb, shp, mid, (float*)d_out);
}